// round 1
// baseline (speedup 1.0000x reference)
#include <cuda_runtime.h>
#include <math.h>

#define BB    4
#define NN    4096
#define FIN   256
#define FOUT  128
#define GALPHA 0.2f

// Scratch (device globals: allocation-free per harness rules)
__device__ __align__(16) float g_Wh[BB * NN * FOUT];   // 8 MB, L2-resident
__device__ float g_Wh1[BB * NN];
__device__ float g_Wh2[BB * NN];

// ---------------------------------------------------------------------------
// Kernel A: Wh = h @ W   (16384 x 256) @ (256 x 128)
// Block: 64 rows x 128 cols, 256 threads, each thread 4x8 accumulators.
// ---------------------------------------------------------------------------
__global__ __launch_bounds__(256) void wh_gemm_kernel(const float* __restrict__ h,
                                                      const float* __restrict__ W) {
    __shared__ float hs[64][33];     // +1 pad: avoid bank conflict on column reads
    __shared__ float Ws[32][FOUT];
    const int t  = threadIdx.x;
    const int r0 = blockIdx.x * 64;
    const int cg = (t & 15) * 8;
    const int rg = (t >> 4) * 4;

    float acc[4][8];
#pragma unroll
    for (int r = 0; r < 4; ++r)
#pragma unroll
        for (int c = 0; c < 8; ++c) acc[r][c] = 0.f;

    for (int kt = 0; kt < FIN; kt += 32) {
#pragma unroll
        for (int i = 0; i < 8; ++i) {
            int e = t + i * 256;
            hs[e >> 5][e & 31] = h[(size_t)(r0 + (e >> 5)) * FIN + kt + (e & 31)];
        }
#pragma unroll
        for (int i = 0; i < 16; ++i) {
            int e = t + i * 256;
            Ws[e >> 7][e & 127] = W[(size_t)(kt + (e >> 7)) * FOUT + (e & 127)];
        }
        __syncthreads();
#pragma unroll
        for (int kk = 0; kk < 32; ++kk) {
            float av[4];
#pragma unroll
            for (int r = 0; r < 4; ++r) av[r] = hs[rg + r][kk];
            float4 b0 = *(const float4*)&Ws[kk][cg];
            float4 b1 = *(const float4*)&Ws[kk][cg + 4];
            float bv[8] = {b0.x, b0.y, b0.z, b0.w, b1.x, b1.y, b1.z, b1.w};
#pragma unroll
            for (int r = 0; r < 4; ++r)
#pragma unroll
                for (int c = 0; c < 8; ++c)
                    acc[r][c] += av[r] * bv[c];
        }
        __syncthreads();
    }
#pragma unroll
    for (int r = 0; r < 4; ++r)
#pragma unroll
        for (int c = 0; c < 8; ++c)
            g_Wh[(size_t)(r0 + rg + r) * FOUT + cg + c] = acc[r][c];
}

// ---------------------------------------------------------------------------
// Kernel B: Wh1 = Wh @ a1, Wh2 = Wh @ a2   (one warp per row)
// ---------------------------------------------------------------------------
__global__ __launch_bounds__(256) void proj_kernel(const float* __restrict__ a) {
    const int row  = blockIdx.x * 8 + (threadIdx.x >> 5);
    const int lane = threadIdx.x & 31;
    const float* wh = g_Wh + (size_t)row * FOUT;
    float s1 = 0.f, s2 = 0.f;
#pragma unroll
    for (int i = 0; i < 4; ++i) {
        int k = lane + 32 * i;
        float v = wh[k];
        s1 += v * a[k];
        s2 += v * a[FOUT + k];
    }
#pragma unroll
    for (int o = 16; o > 0; o >>= 1) {
        s1 += __shfl_down_sync(0xffffffffu, s1, o);
        s2 += __shfl_down_sync(0xffffffffu, s2, o);
    }
    if (lane == 0) { g_Wh1[row] = s1; g_Wh2[row] = s2; }
}

// ---------------------------------------------------------------------------
// Kernel C: fused masked-LeakyReLU-softmax + (attention @ Wh) + ELU
// Block: 64 n-rows x 128 features, m-tiles of 128. 256 threads.
// Unnormalized weight via exp factorization:
//   s = Wh1[n] + Wh2[m];  exp(leakyrelu(s)) = s>=0 ? EP[n]*cpos[m] : EN[n]*cneg[m]
// so the per-pair cost is compare+select+mul (no MUFU in the hot loop).
// Accumulate num[64][128] and den[64] in one pass; out = elu(num/den).
// ---------------------------------------------------------------------------
__global__ __launch_bounds__(256, 2) void gat_attn_kernel(const int* __restrict__ adj,
                                                          float* __restrict__ out) {
    extern __shared__ float sm[];
    float* Whs  = sm;                      // [128][128]  64 KB
    float* ws   = Whs + 128 * 128;         // [64][128]   32 KB (weights per tile)
    float* wh1s = ws + 64 * 128;           // [64]
    float* eps  = wh1s + 64;               // [64]  exp(Wh1)
    float* ens  = eps + 64;                // [64]  exp(alpha*Wh1)
    float* wh2s = ens + 64;                // [128]
    float* cps  = wh2s + 128;              // [128] exp(Wh2)
    float* cns  = cps + 128;               // [128] exp(alpha*Wh2)

    const int t  = threadIdx.x;
    const int b  = blockIdx.y;
    const int n0 = blockIdx.x * 64;
    const int cg = (t & 15) * 8;           // feature group (8 cols)
    const int rl = (t >> 4) * 4;           // row group (4 rows)

    if (t < 64) {
        float w1 = g_Wh1[b * NN + n0 + t];
        wh1s[t] = w1;
        eps[t]  = __expf(w1);
        ens[t]  = __expf(GALPHA * w1);
    }

    const int* adjbase = adj + (size_t)(b * NN + n0) * NN;

    float acc[4][8];
#pragma unroll
    for (int r = 0; r < 4; ++r)
#pragma unroll
        for (int c = 0; c < 8; ++c) acc[r][c] = 0.f;
    float den[4] = {0.f, 0.f, 0.f, 0.f};

    for (int mt = 0; mt < NN; mt += 128) {
        __syncthreads();  // previous-tile consumers done (also orders preamble)

        // Stage Wh[m-tile] (128x128 floats) via float4
        const float4* src = (const float4*)(g_Wh + (size_t)(b * NN + mt) * FOUT);
        float4* dst = (float4*)Whs;
#pragma unroll
        for (int i = 0; i < 16; ++i) dst[t + i * 256] = src[t + i * 256];

        if (t < 128) {
            float w2 = g_Wh2[b * NN + mt + t];
            wh2s[t] = w2;
            cps[t]  = __expf(w2);
            cns[t]  = __expf(GALPHA * w2);
        }
        __syncthreads();

        // Compute weight tile ws[64][128] (adj via int4, coalesced)
#pragma unroll
        for (int i = 0; i < 8; ++i) {
            int idx4 = t + i * 256;        // 0..2047 groups of 4
            int row  = idx4 >> 5;          // 32 int4-groups per row
            int j4   = (idx4 & 31) << 2;
            int4 av  = *(const int4*)(adjbase + (size_t)row * NN + mt + j4);
            float w1 = wh1s[row];
            float ep = eps[row], en = ens[row];
            float4 w2v = *(const float4*)&wh2s[j4];
            float4 cpv = *(const float4*)&cps[j4];
            float4 cnv = *(const float4*)&cns[j4];
            float4 wv;
            wv.x = (av.x > 0) ? ((w1 + w2v.x >= 0.f) ? cpv.x * ep : cnv.x * en) : 0.f;
            wv.y = (av.y > 0) ? ((w1 + w2v.y >= 0.f) ? cpv.y * ep : cnv.y * en) : 0.f;
            wv.z = (av.z > 0) ? ((w1 + w2v.z >= 0.f) ? cpv.z * ep : cnv.z * en) : 0.f;
            wv.w = (av.w > 0) ? ((w1 + w2v.w >= 0.f) ? cpv.w * ep : cnv.w * en) : 0.f;
            *(float4*)&ws[row * 128 + j4] = wv;
        }
        __syncthreads();

        // FFMA-bound rank-128 update: per j, 12 smem B + 36 FFMA/FADD per thread
#pragma unroll 8
        for (int j = 0; j < 128; ++j) {
            float wr[4];
            wr[0] = ws[(rl + 0) * 128 + j];
            wr[1] = ws[(rl + 1) * 128 + j];
            wr[2] = ws[(rl + 2) * 128 + j];
            wr[3] = ws[(rl + 3) * 128 + j];
            float4 p0 = *(const float4*)&Whs[j * 128 + cg];
            float4 p1 = *(const float4*)&Whs[j * 128 + cg + 4];
            float pv[8] = {p0.x, p0.y, p0.z, p0.w, p1.x, p1.y, p1.z, p1.w};
#pragma unroll
            for (int r = 0; r < 4; ++r) {
#pragma unroll
                for (int c = 0; c < 8; ++c)
                    acc[r][c] += wr[r] * pv[c];
                den[r] += wr[r];
            }
        }
    }

    // Epilogue: normalize + ELU
#pragma unroll
    for (int r = 0; r < 4; ++r) {
        float inv = 1.f / den[r];
#pragma unroll
        for (int c = 0; c < 8; ++c) {
            float y = acc[r][c] * inv;
            y = (y > 0.f) ? y : expm1f(y);
            out[(size_t)(b * NN + n0 + rl + r) * FOUT + cg + c] = y;
        }
    }
}

// ---------------------------------------------------------------------------
extern "C" void kernel_launch(void* const* d_in, const int* in_sizes, int n_in,
                              void* d_out, int out_size) {
    const float* h   = (const float*)d_in[0];
    const int*   adj = (const int*)d_in[1];
    const float* W   = (const float*)d_in[2];
    const float* a   = (const float*)d_in[3];
    float* out = (float*)d_out;

    wh_gemm_kernel<<<(BB * NN) / 64, 256>>>(h, W);
    proj_kernel<<<(BB * NN) / 8, 256>>>(a);

    const int smem_bytes = (128 * 128 + 64 * 128 + 64 * 3 + 128 * 3) * (int)sizeof(float);
    cudaFuncSetAttribute(gat_attn_kernel,
                         cudaFuncAttributeMaxDynamicSharedMemorySize, smem_bytes);
    gat_attn_kernel<<<dim3(NN / 64, BB), 256, smem_bytes>>>(adj, out);
}

// round 3
// speedup vs baseline: 2.2847x; 2.2847x over previous
#include <cuda_runtime.h>
#include <cuda_bf16.h>
#include <math.h>
#include <cstdint>

#define BB    4
#define NN    4096
#define FIN   256
#define FOUT  128
#define GALPHA 0.2f

#define KT      64                 // m-columns per tile
#define NTILES  (NN / KT)          // 64
#define ASTRIDE 72                 // bf16 elems per smem row (64 + 8 pad)

// ---- device scratch (no allocations allowed) ----
__device__ __align__(16) float g_Wh[BB * NN * FOUT];            // [b][m][f] fp32
__device__ __align__(16) __nv_bfloat16 g_WhTh[BB * FOUT * NN];  // [b][f][m] hi
__device__ __align__(16) __nv_bfloat16 g_WhTl[BB * FOUT * NN];  // [b][f][m] lo
__device__ float g_Wh1[BB * NN];
__device__ float g_Wh2[BB * NN];

// ---------------------------------------------------------------------------
// PTX helpers (all plain-sm_80+ instructions: safe for .target sm_103)
// ---------------------------------------------------------------------------
__device__ __forceinline__ uint32_t smem_u32(const void* p) {
    uint32_t a;
    asm("{ .reg .u64 t; cvta.to.shared.u64 t, %1; cvt.u32.u64 %0, t; }" : "=r"(a) : "l"(p));
    return a;
}
__device__ __forceinline__ void cp16(uint32_t saddr, const void* g) {
    asm volatile("cp.async.cg.shared.global [%0], [%1], 16;" :: "r"(saddr), "l"(g));
}
__device__ __forceinline__ void cp_commit() { asm volatile("cp.async.commit_group;"); }
__device__ __forceinline__ void cp_wait0()  { asm volatile("cp.async.wait_group 0;"); }

__device__ __forceinline__ void ldsm_x4(uint32_t* r, uint32_t addr) {
    asm volatile("ldmatrix.sync.aligned.m8n8.x4.shared.b16 {%0,%1,%2,%3}, [%4];"
                 : "=r"(r[0]), "=r"(r[1]), "=r"(r[2]), "=r"(r[3]) : "r"(addr));
}
__device__ __forceinline__ void mma16816(float* c, const uint32_t* a, uint32_t b0, uint32_t b1) {
    asm volatile(
        "mma.sync.aligned.m16n8k16.row.col.f32.bf16.bf16.f32 "
        "{%0,%1,%2,%3}, {%4,%5,%6,%7}, {%8,%9}, {%0,%1,%2,%3};"
        : "+f"(c[0]), "+f"(c[1]), "+f"(c[2]), "+f"(c[3])
        : "r"(a[0]), "r"(a[1]), "r"(a[2]), "r"(a[3]), "r"(b0), "r"(b1));
}

// ---------------------------------------------------------------------------
// Kernel A: Wh = h @ W (unchanged)
// ---------------------------------------------------------------------------
__global__ __launch_bounds__(256) void wh_gemm_kernel(const float* __restrict__ h,
                                                      const float* __restrict__ W) {
    __shared__ float hs[64][33];
    __shared__ float Ws[32][FOUT];
    const int t  = threadIdx.x;
    const int r0 = blockIdx.x * 64;
    const int cg = (t & 15) * 8;
    const int rg = (t >> 4) * 4;

    float acc[4][8];
#pragma unroll
    for (int r = 0; r < 4; ++r)
#pragma unroll
        for (int c = 0; c < 8; ++c) acc[r][c] = 0.f;

    for (int kt = 0; kt < FIN; kt += 32) {
#pragma unroll
        for (int i = 0; i < 8; ++i) {
            int e = t + i * 256;
            hs[e >> 5][e & 31] = h[(size_t)(r0 + (e >> 5)) * FIN + kt + (e & 31)];
        }
#pragma unroll
        for (int i = 0; i < 16; ++i) {
            int e = t + i * 256;
            Ws[e >> 7][e & 127] = W[(size_t)(kt + (e >> 7)) * FOUT + (e & 127)];
        }
        __syncthreads();
#pragma unroll
        for (int kk = 0; kk < 32; ++kk) {
            float av[4];
#pragma unroll
            for (int r = 0; r < 4; ++r) av[r] = hs[rg + r][kk];
            float4 b0 = *(const float4*)&Ws[kk][cg];
            float4 b1 = *(const float4*)&Ws[kk][cg + 4];
            float bv[8] = {b0.x, b0.y, b0.z, b0.w, b1.x, b1.y, b1.z, b1.w};
#pragma unroll
            for (int r = 0; r < 4; ++r)
#pragma unroll
                for (int c = 0; c < 8; ++c)
                    acc[r][c] += av[r] * bv[c];
        }
        __syncthreads();
    }
#pragma unroll
    for (int r = 0; r < 4; ++r)
#pragma unroll
        for (int c = 0; c < 8; ++c)
            g_Wh[(size_t)(r0 + rg + r) * FOUT + cg + c] = acc[r][c];
}

// ---------------------------------------------------------------------------
// Kernel B: Wh1/Wh2 projections (unchanged)
// ---------------------------------------------------------------------------
__global__ __launch_bounds__(256) void proj_kernel(const float* __restrict__ a) {
    const int row  = blockIdx.x * 8 + (threadIdx.x >> 5);
    const int lane = threadIdx.x & 31;
    const float* wh = g_Wh + (size_t)row * FOUT;
    float s1 = 0.f, s2 = 0.f;
#pragma unroll
    for (int i = 0; i < 4; ++i) {
        int k = lane + 32 * i;
        float v = wh[k];
        s1 += v * a[k];
        s2 += v * a[FOUT + k];
    }
#pragma unroll
    for (int o = 16; o > 0; o >>= 1) {
        s1 += __shfl_down_sync(0xffffffffu, s1, o);
        s2 += __shfl_down_sync(0xffffffffu, s2, o);
    }
    if (lane == 0) { g_Wh1[row] = s1; g_Wh2[row] = s2; }
}

// ---------------------------------------------------------------------------
// Kernel B2: WhT hi/lo bf16 split:  g_WhTh/l[b][f][m] = split(Wh[b][m][f])
// ---------------------------------------------------------------------------
__global__ __launch_bounds__(256) void transpose_split_kernel() {
    __shared__ float tile[32][33];
    const int tx = threadIdx.x, ty = threadIdx.y;
    const int m0 = blockIdx.x * 32;
    const int f0 = blockIdx.y * 32;
    const int b  = blockIdx.z;
#pragma unroll
    for (int k = 0; k < 4; ++k)
        tile[ty + k * 8][tx] = g_Wh[(size_t)(b * NN + m0 + ty + k * 8) * FOUT + f0 + tx];
    __syncthreads();
#pragma unroll
    for (int k = 0; k < 4; ++k) {
        float v = tile[tx][ty + k * 8];
        __nv_bfloat16 hi = __float2bfloat16(v);
        __nv_bfloat16 lo = __float2bfloat16(v - __bfloat162float(hi));
        size_t o = (size_t)(b * FOUT + f0 + ty + k * 8) * NN + m0 + tx;
        g_WhTh[o] = hi;
        g_WhTl[o] = lo;
    }
}

// ---------------------------------------------------------------------------
// Kernel C: fused mask+softmax+PV via mma.sync bf16 (3-pass hi/lo split)
//   CTA: 128 n-rows x 128 features, K-tiles of 64, 8 warps (2 M x 4 N),
//   each warp 64x32 via m16n8k16 fragments. adj + B double-buffered cp.async.
// ---------------------------------------------------------------------------
#define TILE_ADJ_B (128 * KT * 4)            // 32768 B
#define TILE_AB    (128 * ASTRIDE * 2)       // 18432 B
#define OFF_ADJ    0                         // 2 x 32768
#define OFF_B0     (2 * TILE_ADJ_B)          // 4 x 18432 (Bh0,Bl0,Bh1,Bl1)
#define OFF_AH     (OFF_B0 + 4 * TILE_AB)
#define OFF_AL     (OFF_AH + TILE_AB)
#define OFF_W2     (OFF_AL + TILE_AB)        // float[4096]
#define OFF_CP     (OFF_W2 + 16384)
#define OFF_CN     (OFF_CP + 16384)
#define OFF_WH1    (OFF_CN + 16384)          // float[128] x4
#define OFF_EPS    (OFF_WH1 + 512)
#define OFF_ENS    (OFF_EPS + 512)
#define OFF_DENS   (OFF_ENS + 512)
#define SMEM_TOTAL (OFF_DENS + 512)          // 227328 B

#define OFF_BH(p) (OFF_B0 + (p) * 2 * TILE_AB)
#define OFF_BL(p) (OFF_BH(p) + TILE_AB)

__global__ __launch_bounds__(256, 1) void gat_attn_mma(const int* __restrict__ adj,
                                                       float* __restrict__ out) {
    extern __shared__ __align__(128) char sm[];
    const uint32_t smb = smem_u32(sm);

    float* w2s  = (float*)(sm + OFF_W2);
    float* cps  = (float*)(sm + OFF_CP);
    float* cns  = (float*)(sm + OFF_CN);
    float* wh1s = (float*)(sm + OFF_WH1);
    float* eps  = (float*)(sm + OFF_EPS);
    float* ens  = (float*)(sm + OFF_ENS);
    float* dens = (float*)(sm + OFF_DENS);

    const int t    = threadIdx.x;
    const int wid  = t >> 5;
    const int lane = t & 31;
    const int b    = blockIdx.y;
    const int n0   = blockIdx.x * 128;
    const int wm   = wid & 1;                // warp M position (0..1)
    const int wn   = wid >> 1;               // warp N position (0..3)

    // ---- prefetch tile 0 (adj + B) ----
    {
        const int mt = 0, p = 0;
#pragma unroll
        for (int j = 0; j < 8; ++j) {
            int idx = t + j * 256;           // 2048 16B-chunks of adj
            int row = idx >> 4, c16 = idx & 15;
            cp16(smb + OFF_ADJ + p * TILE_ADJ_B + idx * 16,
                 adj + (size_t)(b * NN + n0 + row) * NN + mt + c16 * 4);
        }
#pragma unroll
        for (int j = 0; j < 4; ++j) {
            int idx = t + j * 256;           // 1024 chunks each split
            int f = idx >> 3, c = idx & 7;
            cp16(smb + OFF_BH(p) + f * (ASTRIDE * 2) + c * 16,
                 g_WhTh + (size_t)(b * FOUT + f) * NN + mt + c * 8);
            cp16(smb + OFF_BL(p) + f * (ASTRIDE * 2) + c * 16,
                 g_WhTl + (size_t)(b * FOUT + f) * NN + mt + c * 8);
        }
        cp_commit();
    }

    // ---- factor tables ----
    for (int m = t; m < NN; m += 256) {
        float w2 = g_Wh2[b * NN + m];
        w2s[m] = w2;
        cps[m] = __expf(w2);
        cns[m] = __expf(GALPHA * w2);
    }
    if (t < 128) {
        float w1 = g_Wh1[b * NN + n0 + t];
        wh1s[t] = w1;
        eps[t]  = __expf(w1);
        ens[t]  = __expf(GALPHA * w1);
    }
    __syncthreads();

    // per-thread weight-gen constants (row r = t>>1, 32 cols each)
    const int   wg_r   = t >> 1;
    const int   wg_c0  = (t & 1) * 32;
    const float myw1 = wh1s[wg_r], myep = eps[wg_r], myen = ens[wg_r];

    // per-thread ldmatrix byte offsets
    const uint32_t a_off = (uint32_t)(((wm * 64 + (lane & 15)) * ASTRIDE + ((lane >> 4) << 3)) * 2);
    const uint32_t b_off = (uint32_t)(((wn * 32 + (lane & 7) + ((lane >> 4) << 3)) * ASTRIDE +
                                      (((lane >> 3) & 1) << 3)) * 2);

    float acc[4][4][4];
#pragma unroll
    for (int i = 0; i < 4; ++i)
#pragma unroll
        for (int j = 0; j < 4; ++j)
#pragma unroll
            for (int k = 0; k < 4; ++k) acc[i][j][k] = 0.f;
    float den = 0.f;

    for (int i = 0; i < NTILES; ++i) {
        const int p  = i & 1;
        const int mt = i * KT;

        cp_wait0();            // tile i staged
        __syncthreads();       // all see smem; prev MMA done with A

        // ---- weight-gen: w -> bf16 hi/lo into Ah/Al, den accumulate ----
        {
            const int* adjs = (const int*)(sm + OFF_ADJ + p * TILE_ADJ_B);
            char* Ah = sm + OFF_AH;
            char* Al = sm + OFF_AL;
#pragma unroll
            for (int g = 0; g < 8; ++g) {
                int c  = wg_c0 + g * 4;
                int m  = mt + c;
                int4 av = *(const int4*)(adjs + wg_r * KT + c);
                float4 w2v = *(const float4*)&w2s[m];
                float4 cpv = *(const float4*)&cps[m];
                float4 cnv = *(const float4*)&cns[m];
                float4 w;
                w.x = (av.x > 0) ? ((myw1 + w2v.x >= 0.f) ? myep * cpv.x : myen * cnv.x) : 0.f;
                w.y = (av.y > 0) ? ((myw1 + w2v.y >= 0.f) ? myep * cpv.y : myen * cnv.y) : 0.f;
                w.z = (av.z > 0) ? ((myw1 + w2v.z >= 0.f) ? myep * cpv.z : myen * cnv.z) : 0.f;
                w.w = (av.w > 0) ? ((myw1 + w2v.w >= 0.f) ? myep * cpv.w : myen * cnv.w) : 0.f;
                den += (w.x + w.y) + (w.z + w.w);
                __nv_bfloat162 h01 = __floats2bfloat162_rn(w.x, w.y);
                __nv_bfloat162 h23 = __floats2bfloat162_rn(w.z, w.w);
                float2 f01 = __bfloat1622float2(h01);
                float2 f23 = __bfloat1622float2(h23);
                __nv_bfloat162 l01 = __floats2bfloat162_rn(w.x - f01.x, w.y - f01.y);
                __nv_bfloat162 l23 = __floats2bfloat162_rn(w.z - f23.x, w.w - f23.y);
                uint32_t off = (uint32_t)(wg_r * (ASTRIDE * 2) + c * 2);
                *(uint2*)(Ah + off) = make_uint2(*(uint32_t*)&h01, *(uint32_t*)&h23);
                *(uint2*)(Al + off) = make_uint2(*(uint32_t*)&l01, *(uint32_t*)&l23);
            }
        }

        // ---- prefetch tile i+1 into other buffers ----
        if (i + 1 < NTILES) {
            const int mtn = mt + KT, pn = p ^ 1;
#pragma unroll
            for (int j = 0; j < 8; ++j) {
                int idx = t + j * 256;
                int row = idx >> 4, c16 = idx & 15;
                cp16(smb + OFF_ADJ + pn * TILE_ADJ_B + idx * 16,
                     adj + (size_t)(b * NN + n0 + row) * NN + mtn + c16 * 4);
            }
#pragma unroll
            for (int j = 0; j < 4; ++j) {
                int idx = t + j * 256;
                int f = idx >> 3, c = idx & 7;
                cp16(smb + OFF_BH(pn) + f * (ASTRIDE * 2) + c * 16,
                     g_WhTh + (size_t)(b * FOUT + f) * NN + mtn + c * 8);
                cp16(smb + OFF_BL(pn) + f * (ASTRIDE * 2) + c * 16,
                     g_WhTl + (size_t)(b * FOUT + f) * NN + mtn + c * 8);
            }
        }
        cp_commit();
        __syncthreads();       // Ah/Al ready

        // ---- MMA phase: 4 k16-steps, 3-pass split ----
        const uint32_t ah_base = smb + OFF_AH + a_off;
        const uint32_t al_base = smb + OFF_AL + a_off;
        const uint32_t bh_base = smb + OFF_BH(p) + b_off;
        const uint32_t bl_base = smb + OFF_BL(p) + b_off;
#pragma unroll
        for (int ks = 0; ks < 4; ++ks) {
            const uint32_t kb = ks * 32;     // k0*2 bytes
            uint32_t ah[4][4], al[4][4], bh[2][4], bl[2][4];
#pragma unroll
            for (int mt4 = 0; mt4 < 4; ++mt4) {
                ldsm_x4(ah[mt4], ah_base + mt4 * (16 * ASTRIDE * 2) + kb);
                ldsm_x4(al[mt4], al_base + mt4 * (16 * ASTRIDE * 2) + kb);
            }
#pragma unroll
            for (int nh = 0; nh < 2; ++nh) {
                ldsm_x4(bh[nh], bh_base + nh * (16 * ASTRIDE * 2) + kb);
                ldsm_x4(bl[nh], bl_base + nh * (16 * ASTRIDE * 2) + kb);
            }
#pragma unroll
            for (int mt4 = 0; mt4 < 4; ++mt4)
#pragma unroll
                for (int nt = 0; nt < 4; ++nt) {
                    const int nh = nt >> 1, sel = (nt & 1) * 2;
                    mma16816(acc[mt4][nt], ah[mt4], bh[nh][sel], bh[nh][sel + 1]);
                    mma16816(acc[mt4][nt], ah[mt4], bl[nh][sel], bl[nh][sel + 1]);
                    mma16816(acc[mt4][nt], al[mt4], bh[nh][sel], bh[nh][sel + 1]);
                }
        }
    }

    // ---- den: pair-reduce (threads t, t^1 share a row) ----
    float dtot = den + __shfl_xor_sync(0xffffffffu, den, 1);
    if ((t & 1) == 0) dens[wg_r] = dtot;
    __syncthreads();

    // ---- epilogue: normalize + ELU + store ----
#pragma unroll
    for (int mt4 = 0; mt4 < 4; ++mt4) {
        const int row0 = wm * 64 + mt4 * 16 + (lane >> 2);
        const float inv0 = 1.f / dens[row0];
        const float inv8 = 1.f / dens[row0 + 8];
        float* o0 = out + (size_t)(b * NN + n0 + row0) * FOUT;
        float* o8 = out + (size_t)(b * NN + n0 + row0 + 8) * FOUT;
#pragma unroll
        for (int nt = 0; nt < 4; ++nt) {
            const int col = wn * 32 + nt * 8 + (lane & 3) * 2;
            float y0 = acc[mt4][nt][0] * inv0;
            float y1 = acc[mt4][nt][1] * inv0;
            float y2 = acc[mt4][nt][2] * inv8;
            float y3 = acc[mt4][nt][3] * inv8;
            float2 v0 = make_float2((y0 > 0.f) ? y0 : expm1f(y0),
                                    (y1 > 0.f) ? y1 : expm1f(y1));
            float2 v8 = make_float2((y2 > 0.f) ? y2 : expm1f(y2),
                                    (y3 > 0.f) ? y3 : expm1f(y3));
            *(float2*)(o0 + col) = v0;
            *(float2*)(o8 + col) = v8;
        }
    }
}

// ---------------------------------------------------------------------------
extern "C" void kernel_launch(void* const* d_in, const int* in_sizes, int n_in,
                              void* d_out, int out_size) {
    const float* h   = (const float*)d_in[0];
    const int*   adj = (const int*)d_in[1];
    const float* W   = (const float*)d_in[2];
    const float* a   = (const float*)d_in[3];
    float* out = (float*)d_out;

    wh_gemm_kernel<<<(BB * NN) / 64, 256>>>(h, W);
    proj_kernel<<<(BB * NN) / 8, 256>>>(a);
    transpose_split_kernel<<<dim3(NN / 32, FOUT / 32, BB), dim3(32, 8)>>>();

    cudaFuncSetAttribute(gat_attn_mma, cudaFuncAttributeMaxDynamicSharedMemorySize, SMEM_TOTAL);
    gat_attn_mma<<<dim3(NN / 128, BB), 256, SMEM_TOTAL>>>(adj, out);
}

// round 4
// speedup vs baseline: 2.6793x; 1.1727x over previous
#include <cuda_runtime.h>
#include <cuda_bf16.h>
#include <math.h>
#include <cstdint>

#define BB    4
#define NN    4096
#define FIN   256
#define FOUT  128
#define GALPHA 0.2f

#define KT      64                 // m-columns per tile
#define NTILES  (NN / KT)          // 64
#define ASTRIDE 72                 // bf16 elems per smem row (64 + 8 pad)
#define AJSTR   68                 // ints per adj smem row (64 + 4 pad)

// ---- device scratch ----
__device__ __align__(16) float g_Wh[BB * NN * FOUT];            // [b][m][f] fp32
__device__ __align__(16) __nv_bfloat16 g_WhTh[BB * FOUT * NN];  // [b][f][m] hi
__device__ __align__(16) __nv_bfloat16 g_WhTl[BB * FOUT * NN];  // [b][f][m] lo
__device__ float g_Wh1[BB * NN];
__device__ __align__(16) float4 g_cf[BB * NN];                  // (w2, e^w2, e^aw2, 0)

// ---------------------------------------------------------------------------
// PTX helpers (plain sm_80+ instructions only: .target sm_103 safe)
// ---------------------------------------------------------------------------
__device__ __forceinline__ uint32_t smem_u32(const void* p) {
    uint32_t a;
    asm("{ .reg .u64 t; cvta.to.shared.u64 t, %1; cvt.u32.u64 %0, t; }" : "=r"(a) : "l"(p));
    return a;
}
__device__ __forceinline__ void cp16(uint32_t saddr, const void* g) {
    asm volatile("cp.async.cg.shared.global [%0], [%1], 16;" :: "r"(saddr), "l"(g));
}
__device__ __forceinline__ void cp_commit() { asm volatile("cp.async.commit_group;"); }
template <int N>
__device__ __forceinline__ void cp_wait() { asm volatile("cp.async.wait_group %0;" :: "n"(N)); }

__device__ __forceinline__ void bar_sync(int id) {
    asm volatile("bar.sync %0, 384;" :: "r"(id) : "memory");
}
__device__ __forceinline__ void bar_arrive(int id) {
    asm volatile("bar.arrive %0, 384;" :: "r"(id) : "memory");
}

__device__ __forceinline__ void ldsm_x4(uint32_t* r, uint32_t addr) {
    asm volatile("ldmatrix.sync.aligned.m8n8.x4.shared.b16 {%0,%1,%2,%3}, [%4];"
                 : "=r"(r[0]), "=r"(r[1]), "=r"(r[2]), "=r"(r[3]) : "r"(addr));
}
__device__ __forceinline__ void mma16816(float* c, const uint32_t* a, uint32_t b0, uint32_t b1) {
    asm volatile(
        "mma.sync.aligned.m16n8k16.row.col.f32.bf16.bf16.f32 "
        "{%0,%1,%2,%3}, {%4,%5,%6,%7}, {%8,%9}, {%0,%1,%2,%3};"
        : "+f"(c[0]), "+f"(c[1]), "+f"(c[2]), "+f"(c[3])
        : "r"(a[0]), "r"(a[1]), "r"(a[2]), "r"(a[3]), "r"(b0), "r"(b1));
}

// ---------------------------------------------------------------------------
// Kernel A: Wh = h @ W (unchanged)
// ---------------------------------------------------------------------------
__global__ __launch_bounds__(256) void wh_gemm_kernel(const float* __restrict__ h,
                                                      const float* __restrict__ W) {
    __shared__ float hs[64][33];
    __shared__ float Ws[32][FOUT];
    const int t  = threadIdx.x;
    const int r0 = blockIdx.x * 64;
    const int cg = (t & 15) * 8;
    const int rg = (t >> 4) * 4;

    float acc[4][8];
#pragma unroll
    for (int r = 0; r < 4; ++r)
#pragma unroll
        for (int c = 0; c < 8; ++c) acc[r][c] = 0.f;

    for (int kt = 0; kt < FIN; kt += 32) {
#pragma unroll
        for (int i = 0; i < 8; ++i) {
            int e = t + i * 256;
            hs[e >> 5][e & 31] = h[(size_t)(r0 + (e >> 5)) * FIN + kt + (e & 31)];
        }
#pragma unroll
        for (int i = 0; i < 16; ++i) {
            int e = t + i * 256;
            Ws[e >> 7][e & 127] = W[(size_t)(kt + (e >> 7)) * FOUT + (e & 127)];
        }
        __syncthreads();
#pragma unroll
        for (int kk = 0; kk < 32; ++kk) {
            float av[4];
#pragma unroll
            for (int r = 0; r < 4; ++r) av[r] = hs[rg + r][kk];
            float4 b0 = *(const float4*)&Ws[kk][cg];
            float4 b1 = *(const float4*)&Ws[kk][cg + 4];
            float bv[8] = {b0.x, b0.y, b0.z, b0.w, b1.x, b1.y, b1.z, b1.w};
#pragma unroll
            for (int r = 0; r < 4; ++r)
#pragma unroll
                for (int c = 0; c < 8; ++c)
                    acc[r][c] += av[r] * bv[c];
        }
        __syncthreads();
    }
#pragma unroll
    for (int r = 0; r < 4; ++r)
#pragma unroll
        for (int c = 0; c < 8; ++c)
            g_Wh[(size_t)(r0 + rg + r) * FOUT + cg + c] = acc[r][c];
}

// ---------------------------------------------------------------------------
// Kernel B: row projections + global column-factor table
// ---------------------------------------------------------------------------
__global__ __launch_bounds__(256) void proj_kernel(const float* __restrict__ a) {
    const int row  = blockIdx.x * 8 + (threadIdx.x >> 5);
    const int lane = threadIdx.x & 31;
    const float* wh = g_Wh + (size_t)row * FOUT;
    float s1 = 0.f, s2 = 0.f;
#pragma unroll
    for (int i = 0; i < 4; ++i) {
        int k = lane + 32 * i;
        float v = wh[k];
        s1 += v * a[k];
        s2 += v * a[FOUT + k];
    }
#pragma unroll
    for (int o = 16; o > 0; o >>= 1) {
        s1 += __shfl_down_sync(0xffffffffu, s1, o);
        s2 += __shfl_down_sync(0xffffffffu, s2, o);
    }
    if (lane == 0) {
        g_Wh1[row] = s1;
        g_cf[row]  = make_float4(s2, __expf(s2), __expf(GALPHA * s2), 0.f);
    }
}

// ---------------------------------------------------------------------------
// Kernel B2: WhT hi/lo bf16 split (unchanged)
// ---------------------------------------------------------------------------
__global__ __launch_bounds__(256) void transpose_split_kernel() {
    __shared__ float tile[32][33];
    const int tx = threadIdx.x, ty = threadIdx.y;
    const int m0 = blockIdx.x * 32;
    const int f0 = blockIdx.y * 32;
    const int b  = blockIdx.z;
#pragma unroll
    for (int k = 0; k < 4; ++k)
        tile[ty + k * 8][tx] = g_Wh[(size_t)(b * NN + m0 + ty + k * 8) * FOUT + f0 + tx];
    __syncthreads();
#pragma unroll
    for (int k = 0; k < 4; ++k) {
        float v = tile[tx][ty + k * 8];
        __nv_bfloat16 hi = __float2bfloat16(v);
        __nv_bfloat16 lo = __float2bfloat16(v - __bfloat162float(hi));
        size_t o = (size_t)(b * FOUT + f0 + ty + k * 8) * NN + m0 + tx;
        g_WhTh[o] = hi;
        g_WhTl[o] = lo;
    }
}

// ---------------------------------------------------------------------------
// Kernel C: warp-specialized fused attention
//   Consumers: warps 0-7 (256 thr), 2Mx4N fragment layout, pure ldsm+MMA.
//   Producers: warps 8-11 (128 thr), thread r owns n-row r: cp.async staging
//   (adj, B hi/lo, col-factors), weight-gen -> A hi/lo, den accumulation.
//   Named barriers: FULL[s]=1+s (prod arrive, cons sync),
//                   EMPTY[s]=3+s (cons arrive, prod sync). Double-buffered.
// ---------------------------------------------------------------------------
#define TILE_AB   (128 * ASTRIDE * 2)     // 18432 B  (one bf16 half-tile)
#define TILE_ADJ  (128 * AJSTR * 4)       // 34816 B
#define OFF_A     0                       // 2 stages x (Ah+Al)
#define OFF_B     (OFF_A + 4 * TILE_AB)   // 2 stages x (Bh+Bl)
#define OFF_ADJ   (OFF_B + 4 * TILE_AB)   // 2 stages
#define OFF_CF    (OFF_ADJ + 2 * TILE_ADJ)// 2 stages x 64 float4
#define OFF_DENS  (OFF_CF + 2048)
#define SMEM_TOTAL (OFF_DENS + 512)       // 219648 B

__global__ __launch_bounds__(384, 1) void gat_attn_ws(const int* __restrict__ adj,
                                                      float* __restrict__ out) {
    extern __shared__ __align__(128) char sm[];
    const uint32_t smb = smem_u32(sm);
    float* dens = (float*)(sm + OFF_DENS);

    const int t    = threadIdx.x;
    const int wid  = t >> 5;
    const int lane = t & 31;
    const int b    = blockIdx.y;
    const int n0   = blockIdx.x * 128;

    if (wid >= 8) {
        // =============================== PRODUCER ===========================
        const int r = t - 256;             // 0..127, owns n-row r
        float w1 = g_Wh1[b * NN + n0 + r];
        const float myw1 = w1;
        const float myep = __expf(w1);
        const float myen = __expf(GALPHA * w1);
        const int* gadj = adj + (size_t)(b * NN + n0 + r) * NN;   // this row's adj

        // preamble: stage adj+cf for tiles 0 and 1, plus one dummy group
#pragma unroll
        for (int s = 0; s < 2; ++s) {
            const int mt = s * KT;
            uint32_t abase = smb + OFF_ADJ + s * TILE_ADJ;
#pragma unroll
            for (int j = 0; j < 16; ++j)   // thread r loads its own row
                cp16(abase + r * (AJSTR * 4) + j * 16, gadj + mt + j * 4);
            if (r < 64)
                cp16(smb + OFF_CF + s * 1024 + r * 16, &g_cf[b * NN + mt + r]);
            cp_commit();
        }
        cp_commit();                       // dummy (uniform wait positions)

        float den = 0.f;
        for (int i = 0; i < NTILES; ++i) {
            const int s  = i & 1;
            const int mt = i * KT;
            if (i >= 2) bar_sync(3 + s);   // EMPTY[s]: consumers done with s

            // --- issue B[s] <- tile i (hi/lo) : group B(i) ---
            {
                uint32_t bh = smb + OFF_B + s * 2 * TILE_AB;
                uint32_t bl = bh + TILE_AB;
#pragma unroll
                for (int j = 0; j < 8; ++j) {
                    int idx = r + j * 128;              // 1024 chunks per half
                    int f = idx >> 3, c = idx & 7;
                    size_t go = (size_t)(b * FOUT + f) * NN + mt + c * 8;
                    cp16(bh + f * (ASTRIDE * 2) + c * 16, g_WhTh + go);
                    cp16(bl + f * (ASTRIDE * 2) + c * 16, g_WhTl + go);
                }
            }
            cp_commit();                   // group B(i)

            cp_wait<3>();                  // ADJ(i)+CF(i) complete
            __syncwarp();

            // --- weight-gen: row r, 64 cols -> A[s] hi/lo ---
            {
                const int4*   arow = (const int4*)(sm + OFF_ADJ + s * TILE_ADJ + r * (AJSTR * 4));
                const float4* cf   = (const float4*)(sm + OFF_CF + s * 1024);
                char* Ah = sm + OFF_A + s * 2 * TILE_AB;
                char* Al = Ah + TILE_AB;
#pragma unroll
                for (int g = 0; g < 16; ++g) {
                    const int c = 4 * g;
                    int4 av = arow[g];
                    float4 f0 = cf[c], f1 = cf[c + 1], f2 = cf[c + 2], f3 = cf[c + 3];
                    float w0 = (av.x > 0) ? ((myw1 + f0.x >= 0.f) ? myep * f0.y : myen * f0.z) : 0.f;
                    float w1v = (av.y > 0) ? ((myw1 + f1.x >= 0.f) ? myep * f1.y : myen * f1.z) : 0.f;
                    float w2v = (av.z > 0) ? ((myw1 + f2.x >= 0.f) ? myep * f2.y : myen * f2.z) : 0.f;
                    float w3v = (av.w > 0) ? ((myw1 + f3.x >= 0.f) ? myep * f3.y : myen * f3.z) : 0.f;
                    den += (w0 + w1v) + (w2v + w3v);
                    __nv_bfloat162 h01 = __floats2bfloat162_rn(w0, w1v);
                    __nv_bfloat162 h23 = __floats2bfloat162_rn(w2v, w3v);
                    float2 fh01 = __bfloat1622float2(h01);
                    float2 fh23 = __bfloat1622float2(h23);
                    __nv_bfloat162 l01 = __floats2bfloat162_rn(w0 - fh01.x, w1v - fh01.y);
                    __nv_bfloat162 l23 = __floats2bfloat162_rn(w2v - fh23.x, w3v - fh23.y);
                    uint32_t off = (uint32_t)(r * (ASTRIDE * 2) + c * 2);
                    *(uint2*)(Ah + off) = make_uint2(*(uint32_t*)&h01, *(uint32_t*)&h23);
                    *(uint2*)(Al + off) = make_uint2(*(uint32_t*)&l01, *(uint32_t*)&l23);
                }
            }

            // --- issue ADJ(i+2)+CF(i+2) into stage s ---
            if (i + 2 < NTILES) {
                const int mtn = mt + 2 * KT;
                uint32_t abase = smb + OFF_ADJ + s * TILE_ADJ;
#pragma unroll
                for (int j = 0; j < 16; ++j)
                    cp16(abase + r * (AJSTR * 4) + j * 16, gadj + mtn + j * 4);
                if (r < 64)
                    cp16(smb + OFF_CF + s * 1024 + r * 16, &g_cf[b * NN + mtn + r]);
            }
            cp_commit();                   // group ADJ(i+2) (possibly empty)

            cp_wait<1>();                  // B(i) complete
            __threadfence_block();         // STS + cp visible before release
            bar_arrive(1 + s);             // FULL[s]
        }
        dens[r] = den;
        __syncthreads();
        // producers done
    } else {
        // =============================== CONSUMER ===========================
        const int wm = wid & 1;            // warp M (0..1)
        const int wn = wid >> 1;           // warp N (0..3)
        const uint32_t a_off = (uint32_t)(((wm * 64 + (lane & 15)) * ASTRIDE +
                                          ((lane >> 4) << 3)) * 2);
        const uint32_t b_off = (uint32_t)(((wn * 32 + (lane & 7) + ((lane >> 4) << 3)) * ASTRIDE +
                                          (((lane >> 3) & 1) << 3)) * 2);

        float acc[4][4][4];
#pragma unroll
        for (int i = 0; i < 4; ++i)
#pragma unroll
            for (int j = 0; j < 4; ++j)
#pragma unroll
                for (int k = 0; k < 4; ++k) acc[i][j][k] = 0.f;

        for (int i = 0; i < NTILES; ++i) {
            const int s = i & 1;
            bar_sync(1 + s);               // FULL[s]

            const uint32_t ah_base = smb + OFF_A + s * 2 * TILE_AB + a_off;
            const uint32_t al_base = ah_base + TILE_AB;
            const uint32_t bh_base = smb + OFF_B + s * 2 * TILE_AB + b_off;
            const uint32_t bl_base = bh_base + TILE_AB;
#pragma unroll
            for (int ks = 0; ks < 4; ++ks) {
                const uint32_t kb = ks * 32;
                uint32_t ah[4][4], al[4][4], bh[2][4], bl[2][4];
#pragma unroll
                for (int m4 = 0; m4 < 4; ++m4) {
                    ldsm_x4(ah[m4], ah_base + m4 * (16 * ASTRIDE * 2) + kb);
                    ldsm_x4(al[m4], al_base + m4 * (16 * ASTRIDE * 2) + kb);
                }
#pragma unroll
                for (int nh = 0; nh < 2; ++nh) {
                    ldsm_x4(bh[nh], bh_base + nh * (16 * ASTRIDE * 2) + kb);
                    ldsm_x4(bl[nh], bl_base + nh * (16 * ASTRIDE * 2) + kb);
                }
#pragma unroll
                for (int m4 = 0; m4 < 4; ++m4)
#pragma unroll
                    for (int nt = 0; nt < 4; ++nt) {
                        const int nh = nt >> 1, sel = (nt & 1) * 2;
                        mma16816(acc[m4][nt], ah[m4], bh[nh][sel], bh[nh][sel + 1]);
                        mma16816(acc[m4][nt], ah[m4], bl[nh][sel], bl[nh][sel + 1]);
                        mma16816(acc[m4][nt], al[m4], bh[nh][sel], bh[nh][sel + 1]);
                    }
            }
            bar_arrive(3 + s);             // EMPTY[s]
        }
        __syncthreads();                   // dens ready

        // ---- epilogue: normalize + ELU + store ----
#pragma unroll
        for (int m4 = 0; m4 < 4; ++m4) {
            const int row0 = wm * 64 + m4 * 16 + (lane >> 2);
            const float inv0 = 1.f / dens[row0];
            const float inv8 = 1.f / dens[row0 + 8];
            float* o0 = out + (size_t)(b * NN + n0 + row0) * FOUT;
            float* o8 = out + (size_t)(b * NN + n0 + row0 + 8) * FOUT;
#pragma unroll
            for (int nt = 0; nt < 4; ++nt) {
                const int col = wn * 32 + nt * 8 + (lane & 3) * 2;
                float y0 = acc[m4][nt][0] * inv0;
                float y1 = acc[m4][nt][1] * inv0;
                float y2 = acc[m4][nt][2] * inv8;
                float y3 = acc[m4][nt][3] * inv8;
                float2 v0 = make_float2((y0 > 0.f) ? y0 : expm1f(y0),
                                        (y1 > 0.f) ? y1 : expm1f(y1));
                float2 v8 = make_float2((y2 > 0.f) ? y2 : expm1f(y2),
                                        (y3 > 0.f) ? y3 : expm1f(y3));
                *(float2*)(o0 + col) = v0;
                *(float2*)(o8 + col) = v8;
            }
        }
    }
}

// ---------------------------------------------------------------------------
extern "C" void kernel_launch(void* const* d_in, const int* in_sizes, int n_in,
                              void* d_out, int out_size) {
    const float* h   = (const float*)d_in[0];
    const int*   adj = (const int*)d_in[1];
    const float* W   = (const float*)d_in[2];
    const float* a   = (const float*)d_in[3];
    float* out = (float*)d_out;

    wh_gemm_kernel<<<(BB * NN) / 64, 256>>>(h, W);
    proj_kernel<<<(BB * NN) / 8, 256>>>(a);
    transpose_split_kernel<<<dim3(NN / 32, FOUT / 32, BB), dim3(32, 8)>>>();

    cudaFuncSetAttribute(gat_attn_ws, cudaFuncAttributeMaxDynamicSharedMemorySize, SMEM_TOTAL);
    gat_attn_ws<<<dim3(NN / 128, BB), 384, SMEM_TOTAL>>>(adj, out);
}